// round 4
// baseline (speedup 1.0000x reference)
#include <cuda_runtime.h>

typedef unsigned long long ull;

#define NB 4
#define NN 256
#define DD 128
#define HH 128
#define TT 8      // 8x8 pair tile
#define KC 32     // k-chunk for W1 staging

// Per-node halves of the first linear layer.
// g_A[b*N+i, h]  = b1[h] + sum_k x[i,k]*W1[k,h]
// g_Bv[b*N+j, h] =         sum_k x[j,k]*W1[128+k,h]
__device__ float g_A[NB * NN * HH];
__device__ float g_Bv[NB * NN * HH];

// ---------- f32x2 helpers ----------
__device__ __forceinline__ ull pack2(float lo, float hi) {
    ull r; asm("mov.b64 %0, {%1,%2};" : "=l"(r) : "f"(lo), "f"(hi)); return r;
}
__device__ __forceinline__ ull dup2(float x) { return pack2(x, x); }
__device__ __forceinline__ void unpack2(ull v, float& lo, float& hi) {
    asm("mov.b64 {%0,%1}, %2;" : "=f"(lo), "=f"(hi) : "l"(v));
}
__device__ __forceinline__ ull ffma2(ull a, ull b, ull c) {
    ull d; asm("fma.rn.f32x2 %0, %1, %2, %3;" : "=l"(d) : "l"(a), "l"(b), "l"(c)); return d;
}
__device__ __forceinline__ ull fmul2(ull a, ull b) {
    ull d; asm("mul.rn.f32x2 %0, %1, %2;" : "=l"(d) : "l"(a), "l"(b)); return d;
}
__device__ __forceinline__ ull fadd2(ull a, ull b) {
    ull d; asm("add.rn.f32x2 %0, %1, %2;" : "=l"(d) : "l"(a), "l"(b)); return d;
}

__device__ __forceinline__ float clip20(float x) { return fminf(fmaxf(x, -20.0f), 20.0f); }
__device__ __forceinline__ float sigm(float x)  { return 1.0f / (1.0f + __expf(-x)); }

// ---------- cp.async helpers ----------
__device__ __forceinline__ void cpasync16(void* dst_smem, const void* src) {
    unsigned d = (unsigned)__cvta_generic_to_shared(dst_smem);
    asm volatile("cp.async.cg.shared.global [%0], [%1], 16;\n" :: "r"(d), "l"(src));
}
__device__ __forceinline__ void cp_commit() { asm volatile("cp.async.commit_group;\n"); }
__device__ __forceinline__ void cp_wait0()  { asm volatile("cp.async.wait_group 0;\n"); }

// ---------- Kernel 1: per-node precompute ----------
__global__ void precompute_ab(const float* __restrict__ X,
                              const float* __restrict__ W1,
                              const float* __restrict__ b1) {
    __shared__ float Xs[8 * DD];
    int r0 = blockIdx.x * 8;
    int h  = threadIdx.x;

    for (int e = h; e < 8 * DD / 4; e += 128)
        ((float4*)Xs)[e] = ((const float4*)(X + r0 * DD))[e];
    __syncthreads();

    float accA[8], accB[8];
#pragma unroll
    for (int r = 0; r < 8; r++) { accA[r] = 0.f; accB[r] = 0.f; }

    for (int k = 0; k < DD; k++) {
        float wa = W1[k * HH + h];
        float wb = W1[(DD + k) * HH + h];
#pragma unroll
        for (int r = 0; r < 8; r++) {
            float x = Xs[r * DD + k];
            accA[r] += x * wa;
            accB[r] += x * wb;
        }
    }
    float bb = b1[h];
#pragma unroll
    for (int r = 0; r < 8; r++) {
        g_A[(r0 + r) * HH + h]  = accA[r] + bb;
        g_Bv[(r0 + r) * HH + h] = accB[r];
    }
}

// ---------- Kernel 2: fused pairwise MLP ----------
struct SmemMain {
    float his[TT * DD];   // 8 i-rows
    float hjT[DD * TT];   // 8 j-rows transposed [k][jj]
    float Wc[KC * HH];    // |hi-hj| weight chunk
    float Wd[KC * HH];    // hi*hj   weight chunk
};
struct SmemEpi {
    float Ai[TT * HH];
    float Bi[TT * HH];
    float Aj[TT * HH];
    float Bj[TT * HH];
    float red[2 * TT * TT * 16];
};
union SmemU { SmemMain m; SmemEpi e; };

__global__ void __launch_bounds__(256, 2)
pair_mlp_kernel(const float* __restrict__ X,
                const float* __restrict__ base,
                const float* __restrict__ comp,
                const float* __restrict__ W1,
                const float* __restrict__ W2,
                const float* __restrict__ b2,
                float* __restrict__ out) {
    int jt = blockIdx.x, it = blockIdx.y, b = blockIdx.z;
    if (jt < it) return;   // lower-triangle tile: partner covers it
    int i0 = it * TT, j0 = jt * TT;
    int tid = threadIdx.x;
    int hg = tid & 15;          // 16 h-groups: h in {hg*4..+3} U {64+hg*4..+3}
    int ii = (tid >> 4) & 7;    // i-row within tile
    int jhalf = tid >> 7;       // jj in [jhalf*4, jhalf*4+4)

    __shared__ __align__(16) SmemU sm;
    __shared__ __align__(16) float Wsc[4 * HH];  // W1 rows 512..515
    __shared__ __align__(16) float W2s[HH];

    const float* Xb = X + b * NN * DD;

    // ---- stage: his, hjT, scalar weights, W2, chunk 0 of Wc/Wd ----
    {
        for (int e = tid; e < TT * DD / 4; e += 256)
            ((float4*)sm.m.his)[e] = ((const float4*)(Xb + i0 * DD))[e];

        for (int e = tid; e < TT * DD / 4; e += 256) {
            int jj = e >> 5;
            int k  = (e & 31) * 4;
            float4 v = *(const float4*)(Xb + (j0 + jj) * DD + k);
            sm.m.hjT[(k + 0) * TT + jj] = v.x;
            sm.m.hjT[(k + 1) * TT + jj] = v.y;
            sm.m.hjT[(k + 2) * TT + jj] = v.z;
            sm.m.hjT[(k + 3) * TT + jj] = v.w;
        }
        for (int e = tid; e < 4 * HH / 4; e += 256)
            ((float4*)Wsc)[e] = ((const float4*)(W1 + 512 * HH))[e];
        if (tid < HH / 4) ((float4*)W2s)[tid] = ((const float4*)W2)[tid];

        // chunk 0 via cp.async
        for (int e = tid; e < KC * HH / 4; e += 256) {
            cpasync16((float4*)sm.m.Wc + e, (const float4*)(W1 + 256 * HH) + e);
            cpasync16((float4*)sm.m.Wd + e, (const float4*)(W1 + 384 * HH) + e);
        }
        cp_commit();
        cp_wait0();
    }
    __syncthreads();

    const ull SGN = 0x8000000080000000ULL;
    const ull ABSM = 0x7FFFFFFF7FFFFFFFULL;

    // acc[pp][h] : f32x2 over jj-pair (jhalf*4 + 2pp, +1)
    ull acc[2][8];
#pragma unroll
    for (int p = 0; p < 2; p++)
#pragma unroll
        for (int h = 0; h < 8; h++) acc[p][h] = 0ULL;

    const float* hisP = sm.m.his + ii * DD;

    for (int c = 0; c < DD / KC; c++) {
#pragma unroll 8
        for (int kk = 0; kk < KC; kk++) {
            int k = c * KC + kk;
            ull hi2 = dup2(hisP[k]);
            ulonglong2 hv = *(const ulonglong2*)(sm.m.hjT + k * TT + jhalf * 4);
            ull hj2[2] = { hv.x, hv.y };
            ull p2[2], a2[2];
#pragma unroll
            for (int pp = 0; pp < 2; pp++) {
                p2[pp] = fmul2(hi2, hj2[pp]);                  // hi*hj
                ull d2 = fadd2(hi2, hj2[pp] ^ SGN);            // hi-hj
                a2[pp] = d2 & ABSM;                            // |hi-hj|
            }
            const float* wcp = sm.m.Wc + kk * HH + hg * 4;
            const float* wdp = sm.m.Wd + kk * HH + hg * 4;
            float4 wcl = *(const float4*)wcp;
            float4 wcu = *(const float4*)(wcp + 64);
            float4 wdl = *(const float4*)wdp;
            float4 wdu = *(const float4*)(wdp + 64);
            float wc[8] = { wcl.x, wcl.y, wcl.z, wcl.w, wcu.x, wcu.y, wcu.z, wcu.w };
            float wd[8] = { wdl.x, wdl.y, wdl.z, wdl.w, wdu.x, wdu.y, wdu.z, wdu.w };
#pragma unroll
            for (int h = 0; h < 8; h++) {
                ull wc2 = dup2(wc[h]);
                ull wd2 = dup2(wd[h]);
#pragma unroll
                for (int pp = 0; pp < 2; pp++) {
                    acc[pp][h] = ffma2(a2[pp], wc2, acc[pp][h]);
                    acc[pp][h] = ffma2(p2[pp], wd2, acc[pp][h]);
                }
            }
        }
        if (c + 1 < DD / KC) {
            __syncthreads();   // all warps done reading current chunk
            for (int e = tid; e < KC * HH / 4; e += 256) {
                cpasync16((float4*)sm.m.Wc + e,
                          (const float4*)(W1 + (256 + (c + 1) * KC) * HH) + e);
                cpasync16((float4*)sm.m.Wd + e,
                          (const float4*)(W1 + (384 + (c + 1) * KC) * HH) + e);
            }
            cp_commit();
            cp_wait0();
            __syncthreads();   // new chunk visible
        }
    }
    __syncthreads();

    // ---- epilogue: stage per-node A/B rows (union overlay safe post-sync) ----
    {
        const float4* asrc  = (const float4*)(g_A  + (b * NN + i0) * HH);
        const float4* bsrc  = (const float4*)(g_Bv + (b * NN + i0) * HH);
        const float4* ajsrc = (const float4*)(g_A  + (b * NN + j0) * HH);
        const float4* bjsrc = (const float4*)(g_Bv + (b * NN + j0) * HH);
        for (int e = tid; e < TT * HH / 4; e += 256) {
            ((float4*)sm.e.Ai)[e] = asrc[e];
            ((float4*)sm.e.Bi)[e] = bsrc[e];
            ((float4*)sm.e.Aj)[e] = ajsrc[e];
            ((float4*)sm.e.Bj)[e] = bjsrc[e];
        }
    }
    __syncthreads();

    int i = i0 + ii;
    const float* baseb = base + b * NN * NN;
    const float* compb = comp + b * NN * NN;

    float ai[8], biv[8];
    {
        const float* p = sm.e.Ai + ii * HH + hg * 4;
        float4 l = *(const float4*)p;
        float4 u = *(const float4*)(p + 64);
        ai[0]=l.x; ai[1]=l.y; ai[2]=l.z; ai[3]=l.w;
        ai[4]=u.x; ai[5]=u.y; ai[6]=u.z; ai[7]=u.w;
        const float* q = sm.e.Bi + ii * HH + hg * 4;
        float4 l2 = *(const float4*)q;
        float4 u2 = *(const float4*)(q + 64);
        biv[0]=l2.x; biv[1]=l2.y; biv[2]=l2.z; biv[3]=l2.w;
        biv[4]=u2.x; biv[5]=u2.y; biv[6]=u2.z; biv[7]=u2.w;
    }

#pragma unroll
    for (int pp = 0; pp < 2; pp++) {
        float Clo[8], Chi[8];
#pragma unroll
        for (int h = 0; h < 8; h++) unpack2(acc[pp][h], Clo[h], Chi[h]);
#pragma unroll
        for (int lane = 0; lane < 2; lane++) {
            int jj = jhalf * 4 + pp * 2 + lane;
            int j = j0 + jj;

            float bij = clip20(baseb[i * NN + j]);
            float sbij = sigm(bij);
            float cij = clip20(compb[i * NN + j]);
            float scij = sigm(cij);
            float bji = clip20(baseb[j * NN + i]);
            float sbji = sigm(bji);
            float cji = clip20(compb[j * NN + i]);
            float scji = sigm(cji);

            float pA = 0.f, pB = 0.f;
#pragma unroll
            for (int l = 0; l < 8; l++) {
                float Cv = lane ? Chi[l] : Clo[l];
                int hl = (l < 4) ? (hg * 4 + l) : (64 + hg * 4 + (l - 4));
                float ws0 = Wsc[0 * HH + hl];
                float ws1 = Wsc[1 * HH + hl];
                float ws2 = Wsc[2 * HH + hl];
                float ws3 = Wsc[3 * HH + hl];
                float w2v = W2s[hl];
                float ajv = sm.e.Aj[jj * HH + hl];
                float bjv = sm.e.Bj[jj * HH + hl];
                float s1 = bij * ws0 + sbij * ws1 + cij * ws2 + scij * ws3;
                float s2 = bji * ws0 + sbji * ws1 + cji * ws2 + scji * ws3;
                float hA = Cv + ai[l] + bjv + s1;    // hdn(i,j)
                float hB = Cv + ajv + biv[l] + s2;   // hdn(j,i)
                pA += fmaxf(hA, 0.f) * w2v;
                pB += fmaxf(hB, 0.f) * w2v;
            }
            sm.e.red[(ii * 8 + jj) * 16 + hg]       = pA;
            sm.e.red[(64 + ii * 8 + jj) * 16 + hg]  = pB;
        }
    }
    __syncthreads();

    if (tid < 64) {
        const float* r0p = sm.e.red + tid * 16;
        const float* r1p = sm.e.red + (64 + tid) * 16;
        float s = 0.f;
#pragma unroll
        for (int g = 0; g < 16; g++) s += r0p[g] + r1p[g];
        float v = 0.5f * s + b2[0];
        int pii = tid >> 3, pjj = tid & 7;
        int gi = i0 + pii, gj = j0 + pjj;
        float* ob = out + b * NN * NN;
        if (gj > gi) {
            ob[gi * NN + gj] = v;
            ob[gj * NN + gi] = v;
        } else if (gj == gi) {
            ob[gi * NN + gi] = -1e9f;
        }
        // gj < gi (diag tiles only): partner thread writes it
    }
}

extern "C" void kernel_launch(void* const* d_in, const int* in_sizes, int n_in,
                              void* d_out, int out_size) {
    const float* X    = (const float*)d_in[0];  // node_latents [4,256,128]
    const float* base = (const float*)d_in[1];  // base_edge_logits [4,256,256]
    const float* comp = (const float*)d_in[2];  // completion_logits [4,256,256]
    const float* W1   = (const float*)d_in[3];  // [516,128]
    const float* b1   = (const float*)d_in[4];  // [128]
    const float* W2   = (const float*)d_in[5];  // [128,1]
    const float* b2   = (const float*)d_in[6];  // [1]
    float* out = (float*)d_out;                 // [4,256,256]

    precompute_ab<<<NB * NN / 8, 128>>>(X, W1, b1);
    dim3 grid(NN / TT, NN / TT, NB);
    pair_mlp_kernel<<<grid, 256>>>(X, base, comp, W1, W2, b2, out);
}

// round 7
// speedup vs baseline: 2.1900x; 2.1900x over previous
#include <cuda_runtime.h>
#include <cuda_bf16.h>
#include <cstdint>

#define NB 4
#define NN 256
#define HH 128
typedef unsigned long long ull;

__device__ float g_A[NB*NN*HH];
__device__ float g_Bv[NB*NN*HH];

// smem byte offsets (dynamic)
#define OFF_F    0          // F image  [128][288] bf16 (swizzled)
#define OFF_W    73728      // Wt image [128][288] bf16 (swizzled)
#define OFF_XJ   147456     // Xj pairs u32 [64][129]
#define OFF_BJ   180480     // Bj pairs u32 [128][66]
#define OFF_HIS  214272     // hi pairs u32 [64]
#define OFF_AI   214528     // f32[128]
#define OFF_W2   215040     // f32[128]
#define OFF_RED  215552     // f32[128][2]
#define SMEM_TOT 216576

__device__ __forceinline__ uint32_t s32(const void* p){
  uint32_t a; asm("{ .reg .u64 t; cvta.to.shared.u64 t, %1; cvt.u32.u64 %0, t; }":"=r"(a):"l"(p)); return a;
}
__device__ __forceinline__ uint32_t foff(uint32_t r, uint32_t k){ // byte offset, k elem idx (mult of 8 for 16B)
  return ((r*576u + k*2u) ^ ((r&7u)<<4));
}
__device__ __forceinline__ uint32_t f2bf(float a,float b){
  __nv_bfloat162 t=__floats2bfloat162_rn(a,b); return *(uint32_t*)&t;
}
#define LDSM4(r0,r1,r2,r3,a) asm volatile( \
  "ldmatrix.sync.aligned.m8n8.x4.shared.b16 {%0,%1,%2,%3},[%4];" \
  :"=r"(r0),"=r"(r1),"=r"(r2),"=r"(r3):"r"(a))
#define MMA16816(c,a,b) asm volatile( \
  "mma.sync.aligned.m16n8k16.row.col.f32.bf16.bf16.f32 " \
  "{%0,%1,%2,%3},{%4,%5,%6,%7},{%8,%9},{%0,%1,%2,%3};" \
  :"+f"((c)[0]),"+f"((c)[1]),"+f"((c)[2]),"+f"((c)[3]) \
  :"r"((a)[0]),"r"((a)[1]),"r"((a)[2]),"r"((a)[3]),"r"((b)[0]),"r"((b)[1]))

// ---- Kernel 1: per-node halves ----
__global__ void precompute_ab(const float* __restrict__ X,
                              const float* __restrict__ W1,
                              const float* __restrict__ b1){
  __shared__ float Xs[8*HH];
  int r0=blockIdx.x*8, h=threadIdx.x;
  for(int e=h;e<8*HH/4;e+=128) ((float4*)Xs)[e]=((const float4*)(X+r0*HH))[e];
  __syncthreads();
  float aA[8],aB[8];
#pragma unroll
  for(int r=0;r<8;r++){aA[r]=0.f;aB[r]=0.f;}
  for(int k=0;k<HH;k++){
    float wa=W1[k*HH+h], wb=W1[(HH+k)*HH+h];
#pragma unroll
    for(int r=0;r<8;r++){float x=Xs[r*HH+k];aA[r]+=x*wa;aB[r]+=x*wb;}
  }
  float bb=b1[h];
#pragma unroll
  for(int r=0;r<8;r++){g_A[(r0+r)*HH+h]=aA[r]+bb; g_Bv[(r0+r)*HH+h]=aB[r];}
}

// ---- Kernel 2: HMMA pairwise GEMM + fused epilogue ----
extern __shared__ __align__(1024) char dynsm[];

__global__ void __launch_bounds__(256,1)
pair_gemm(const float* __restrict__ X,const float* __restrict__ base,
          const float* __restrict__ comp,const float* __restrict__ W1,
          const float* __restrict__ W2,const float* __restrict__ b2,
          float* __restrict__ out){
  char* sm=dynsm;
  uint32_t smb=s32(sm);
  int tid=threadIdx.x, w=tid>>5, lane=tid&31;
  int jt=blockIdx.x, ig=blockIdx.y, b=blockIdx.z;
  int j0=jt*128;
  int jw=(w&3)*32, hw=(w>>2)*64;
  float b2v=b2[0];

  // ---- once: W image main k 0..255 ----
  {
    int h=tid&127, halfk=tid>>7;
    for(int c8=0;c8<16;c8++){
      int k0=halfk*128+c8*8;
      uint32_t v[4];
#pragma unroll
      for(int q=0;q<4;q++)
        v[q]=f2bf(W1[(256+k0+2*q)*HH+h], W1[(256+k0+2*q+1)*HH+h]);
      *(float4*)(sm+OFF_W+foff(h,k0))=*(float4*)v;
    }
    if(tid<128){ // W scalar cols 256-263 + zeros 264-271; F zero cols 264-271
      uint32_t v[4]={f2bf(W1[512*HH+h],W1[513*HH+h]),
                     f2bf(W1[514*HH+h],W1[515*HH+h]),0u,0u};
      *(float4*)(sm+OFF_W+foff(h,256))=*(float4*)v;
      uint32_t z[4]={0u,0u,0u,0u};
      *(float4*)(sm+OFF_W+foff(h,264))=*(float4*)z;
      *(float4*)(sm+OFF_F+foff(h,264))=*(float4*)z;
    }
  }
  // ---- once: Xj pairs [kp][j], Bj pairs [j][hp] ----
  for(int idx=tid;idx<64*128;idx+=256){
    int kp=idx&63, j=idx>>6;
    float2 xv=*(const float2*)(X+(size_t)(b*NN+j0+j)*HH+2*kp);
    *(uint32_t*)(sm+OFF_XJ+(kp*129+j)*4)=f2bf(xv.x,xv.y);
  }
  for(int idx=tid;idx<64*128;idx+=256){
    int hp=idx&63, j=idx>>6;
    float2 bv=*(const float2*)(g_Bv+(size_t)(b*NN+j0+j)*HH+2*hp);
    *(uint32_t*)(sm+OFF_BJ+(j*66+hp)*4)=f2bf(bv.x,bv.y);
  }
  if(tid<32) ((float4*)(sm+OFF_W2))[tid]=((const float4*)W2)[tid];
  __syncthreads();

  // ldmatrix per-lane bases (byte offsets w/o swizzle; XOR applied per access)
  uint32_t xr=(uint32_t)((lane&7)<<4);
  uint32_t offA = OFF_F + (uint32_t)(jw+(lane&15))*576u + (uint32_t)((lane>>4)*8)*2u;
  uint32_t offB[4];
#pragma unroll
  for(int q=0;q<4;q++){
    uint32_t rB=(uint32_t)(hw + q*16 + (lane&7) + ((lane>>4)<<3));
    offB[q]= OFF_W + rB*576u + (uint32_t)(((lane>>3)&1)*8)*2u;
  }

  for(int itn=0;itn<16;itn++){
    int i=ig*16+itn;
    // stage hi pairs + Ai
    if(tid<64){
      float2 xv=*(const float2*)(X+(size_t)(b*NN+i)*HH+2*tid);
      *(uint32_t*)(sm+OFF_HIS+tid*4)=f2bf(xv.x,xv.y);
    } else if(tid>=64&&tid<96){
      ((float4*)(sm+OFF_AI))[tid-64]=((const float4*)(g_A+(size_t)(b*NN+i)*HH))[tid-64];
    }
    __syncthreads();

    // build F: sec0 k 0-127 |hi-hj|, sec1 k 128-255 hi*hj
    {
      int j=tid&127, sec=tid>>7;
      for(int c8=0;c8<16;c8++){
        uint32_t v[4];
#pragma unroll
        for(int q=0;q<4;q++){
          int kp=c8*4+q;
          __nv_bfloat162 h2=*(__nv_bfloat162*)(sm+OFF_HIS+kp*4);
          __nv_bfloat162 x2=*(__nv_bfloat162*)(sm+OFF_XJ+(kp*129+j)*4);
          __nv_bfloat162 r=sec?__hmul2(h2,x2):__habs2(__hsub2(h2,x2));
          v[q]=*(uint32_t*)&r;
        }
        *(float4*)(sm+OFF_F+foff((uint32_t)j,(uint32_t)(sec*128+c8*8)))=*(float4*)v;
      }
      if(tid<128){ // scalar feats cols 256-263
        float bv=fminf(fmaxf(base[((size_t)(b*NN)+i)*NN+j0+j],-20.f),20.f);
        float cv=fminf(fmaxf(comp[((size_t)(b*NN)+i)*NN+j0+j],-20.f),20.f);
        float sb=1.f/(1.f+__expf(-bv)), sc=1.f/(1.f+__expf(-cv));
        uint32_t v[4]={f2bf(bv,sb),f2bf(cv,sc),0u,0u};
        *(float4*)(sm+OFF_F+foff((uint32_t)j,256))=*(float4*)v;
      }
    }
    __syncthreads();

    // ---- GEMM: 17 k-steps of m16n8k16 ----
    float c[2][8][4];
#pragma unroll
    for(int mt=0;mt<2;mt++)
#pragma unroll
      for(int nt=0;nt<8;nt++)
#pragma unroll
        for(int e=0;e<4;e++) c[mt][nt][e]=0.f;

    for(int ks=0;ks<17;ks++){
      uint32_t k2=(uint32_t)ks*32u;
      uint32_t a[2][4], bf[8][2];
      LDSM4(a[0][0],a[0][1],a[0][2],a[0][3], smb+((offA+k2)^xr));
      LDSM4(a[1][0],a[1][1],a[1][2],a[1][3], smb+((offA+16*576u+k2)^xr));
#pragma unroll
      for(int q=0;q<4;q++){
        LDSM4(bf[2*q][0],bf[2*q][1],bf[2*q+1][0],bf[2*q+1][1], smb+((offB[q]+k2)^xr));
      }
#pragma unroll
      for(int mt=0;mt<2;mt++)
#pragma unroll
        for(int nt=0;nt<8;nt++)
          MMA16816(c[mt][nt],a[mt],bf[nt]);
    }

    // ---- epilogue ----
    {
      int ch=hw>>6;
      float p[4];
#pragma unroll
      for(int r=0;r<4;r++) p[r]=0.f;
#pragma unroll
      for(int mt=0;mt<2;mt++){
#pragma unroll
        for(int rh=0;rh<2;rh++){
          int j=jw+mt*16+rh*8+(lane>>2);
#pragma unroll
          for(int nt=0;nt<8;nt++){
            int hb=hw+nt*8+2*(lane&3);
            float2 ai=*(float2*)(sm+OFF_AI+hb*4);
            float2 w2=*(float2*)(sm+OFF_W2+hb*4);
            float2 bj=__bfloat1622float2(*(__nv_bfloat162*)(sm+OFF_BJ+(j*66+(hb>>1))*4));
            p[mt*2+rh]+=fmaxf(c[mt][nt][rh*2]  +ai.x+bj.x,0.f)*w2.x
                       +fmaxf(c[mt][nt][rh*2+1]+ai.y+bj.y,0.f)*w2.y;
          }
        }
      }
#pragma unroll
      for(int r=0;r<4;r++){
        p[r]+=__shfl_xor_sync(0xffffffffu,p[r],1);
        p[r]+=__shfl_xor_sync(0xffffffffu,p[r],2);
      }
      if((lane&3)==0){
#pragma unroll
        for(int r=0;r<4;r++){
          int j=jw+(r>>1)*16+(r&1)*8+(lane>>2);
          *(float*)(sm+OFF_RED+(j*2+ch)*4)=p[r];
        }
      }
    }
    __syncthreads();
    if(tid<128){
      float v=*(float*)(sm+OFF_RED+tid*8)+*(float*)(sm+OFF_RED+tid*8+4)+b2v;
      out[((size_t)(b*NN)+i)*NN+j0+tid]=v;
    }
    __syncthreads();
  }
}

// ---- Kernel 3: symmetrize + diagonal ----
__global__ void symmetrize(float* __restrict__ out){
  int idx=blockIdx.x*256+threadIdx.x;
  int b=idx>>16, r=idx&65535, i=r>>8, j=r&255;
  float* ob=out+(size_t)b*NN*NN;
  if(j>i){
    float v=0.5f*(ob[i*NN+j]+ob[j*NN+i]);
    ob[i*NN+j]=v; ob[j*NN+i]=v;
  } else if(j==i) ob[i*NN+i]=-1e9f;
}

extern "C" void kernel_launch(void* const* d_in, const int* in_sizes, int n_in,
                              void* d_out, int out_size){
  const float* X   =(const float*)d_in[0];
  const float* base=(const float*)d_in[1];
  const float* comp=(const float*)d_in[2];
  const float* W1  =(const float*)d_in[3];
  const float* b1  =(const float*)d_in[4];
  const float* W2  =(const float*)d_in[5];
  const float* b2  =(const float*)d_in[6];
  float* out=(float*)d_out;

  precompute_ab<<<NB*NN/8,128>>>(X,W1,b1);
  cudaFuncSetAttribute(pair_gemm,cudaFuncAttributeMaxDynamicSharedMemorySize,SMEM_TOT);
  dim3 g(2,16,NB);
  pair_gemm<<<g,256,SMEM_TOT>>>(X,base,comp,W1,W2,b2,out);
  symmetrize<<<NB*NN*NN/256,256>>>(out);
}

// round 8
// speedup vs baseline: 2.2653x; 1.0344x over previous
#include <cuda_runtime.h>
#include <cuda_bf16.h>
#include <cstdint>

#define NB 4
#define NN 256
#define HH 128
typedef unsigned long long ull;

__device__ float g_A[NB*NN*HH];
__device__ float g_Bv[NB*NN*HH];

// smem byte offsets (dynamic)
#define OFF_F    0          // F image  [128][288] bf16 (swizzled)
#define OFF_W    73728      // Wt image [128][288] bf16 (swizzled)
#define OFF_XJ   147456     // Xj pairs u32 [64][129]
#define OFF_BJ   180480     // Bj pairs u32 [128][66]
#define OFF_HIS  214272     // hi pairs u32 [64]
#define OFF_AI   214528     // f32[128]
#define OFF_W2   215040     // f32[128]
#define OFF_RED  215552     // f32[128][2]
#define SMEM_TOT 216576

__device__ __forceinline__ uint32_t s32(const void* p){
  uint32_t a; asm("{ .reg .u64 t; cvta.to.shared.u64 t, %1; cvt.u32.u64 %0, t; }":"=r"(a):"l"(p)); return a;
}
__device__ __forceinline__ uint32_t foff(uint32_t r, uint32_t k){
  return ((r*576u + k*2u) ^ ((r&7u)<<4));
}
__device__ __forceinline__ uint32_t f2bf(float a,float b){
  __nv_bfloat162 t=__floats2bfloat162_rn(a,b); return *(uint32_t*)&t;
}
#define LDSM4(r0,r1,r2,r3,a) asm volatile( \
  "ldmatrix.sync.aligned.m8n8.x4.shared.b16 {%0,%1,%2,%3},[%4];" \
  :"=r"(r0),"=r"(r1),"=r"(r2),"=r"(r3):"r"(a))
#define MMA16816(c,a,b) asm volatile( \
  "mma.sync.aligned.m16n8k16.row.col.f32.bf16.bf16.f32 " \
  "{%0,%1,%2,%3},{%4,%5,%6,%7},{%8,%9},{%0,%1,%2,%3};" \
  :"+f"((c)[0]),"+f"((c)[1]),"+f"((c)[2]),"+f"((c)[3]) \
  :"r"((a)[0]),"r"((a)[1]),"r"((a)[2]),"r"((a)[3]),"r"((b)[0]),"r"((b)[1]))

// ---- Kernel 1: per-node halves (re-parallelized: 256 blocks x 256 thr) ----
__global__ void __launch_bounds__(256)
precompute_ab(const float* __restrict__ X,
              const float* __restrict__ W1,
              const float* __restrict__ b1){
  __shared__ float Xs[4*HH];
  int r0=blockIdx.x*4;
  int h=threadIdx.x&127, s=threadIdx.x>>7;   // s=0 -> A half, s=1 -> B half
  for(int e=threadIdx.x; e<4*HH/4; e+=256)
    ((float4*)Xs)[e]=((const float4*)(X+(size_t)r0*HH))[e];
  __syncthreads();
  float acc[4]={0.f,0.f,0.f,0.f};
  const float* Wp = W1 + (size_t)s*HH*HH + h;
#pragma unroll 8
  for(int k=0;k<HH;k++){
    float wv = Wp[(size_t)k*HH];
#pragma unroll
    for(int r=0;r<4;r++) acc[r]+=Xs[r*HH+k]*wv;
  }
  if(s==0){
    float bb=b1[h];
#pragma unroll
    for(int r=0;r<4;r++) g_A[(size_t)(r0+r)*HH+h]=acc[r]+bb;
  } else {
#pragma unroll
    for(int r=0;r<4;r++) g_Bv[(size_t)(r0+r)*HH+h]=acc[r];
  }
}

// ---- Kernel 2: HMMA pairwise GEMM + fused epilogue (unchanged, validated) ----
extern __shared__ __align__(1024) char dynsm[];

__global__ void __launch_bounds__(256,1)
pair_gemm(const float* __restrict__ X,const float* __restrict__ base,
          const float* __restrict__ comp,const float* __restrict__ W1,
          const float* __restrict__ W2,const float* __restrict__ b2,
          float* __restrict__ out){
  char* sm=dynsm;
  uint32_t smb=s32(sm);
  int tid=threadIdx.x, w=tid>>5, lane=tid&31;
  int jt=blockIdx.x, ig=blockIdx.y, b=blockIdx.z;
  int j0=jt*128;
  int jw=(w&3)*32, hw=(w>>2)*64;
  float b2v=b2[0];

  // ---- once: W image main k 0..255 ----
  {
    int h=tid&127, halfk=tid>>7;
    for(int c8=0;c8<16;c8++){
      int k0=halfk*128+c8*8;
      uint32_t v[4];
#pragma unroll
      for(int q=0;q<4;q++)
        v[q]=f2bf(W1[(256+k0+2*q)*HH+h], W1[(256+k0+2*q+1)*HH+h]);
      *(float4*)(sm+OFF_W+foff(h,k0))=*(float4*)v;
    }
    if(tid<128){
      uint32_t v[4]={f2bf(W1[512*HH+h],W1[513*HH+h]),
                     f2bf(W1[514*HH+h],W1[515*HH+h]),0u,0u};
      *(float4*)(sm+OFF_W+foff(h,256))=*(float4*)v;
      uint32_t z[4]={0u,0u,0u,0u};
      *(float4*)(sm+OFF_W+foff(h,264))=*(float4*)z;
      *(float4*)(sm+OFF_F+foff(h,264))=*(float4*)z;
    }
  }
  // ---- once: Xj pairs [kp][j], Bj pairs [j][hp] ----
  for(int idx=tid;idx<64*128;idx+=256){
    int kp=idx&63, j=idx>>6;
    float2 xv=*(const float2*)(X+(size_t)(b*NN+j0+j)*HH+2*kp);
    *(uint32_t*)(sm+OFF_XJ+(kp*129+j)*4)=f2bf(xv.x,xv.y);
  }
  for(int idx=tid;idx<64*128;idx+=256){
    int hp=idx&63, j=idx>>6;
    float2 bv=*(const float2*)(g_Bv+(size_t)(b*NN+j0+j)*HH+2*hp);
    *(uint32_t*)(sm+OFF_BJ+(j*66+hp)*4)=f2bf(bv.x,bv.y);
  }
  if(tid<32) ((float4*)(sm+OFF_W2))[tid]=((const float4*)W2)[tid];
  __syncthreads();

  uint32_t xr=(uint32_t)((lane&7)<<4);
  uint32_t offA = OFF_F + (uint32_t)(jw+(lane&15))*576u + (uint32_t)((lane>>4)*8)*2u;
  uint32_t offB[4];
#pragma unroll
  for(int q=0;q<4;q++){
    uint32_t rB=(uint32_t)(hw + q*16 + (lane&7) + ((lane>>4)<<3));
    offB[q]= OFF_W + rB*576u + (uint32_t)(((lane>>3)&1)*8)*2u;
  }

  for(int itn=0;itn<16;itn++){
    int i=ig*16+itn;
    if(tid<64){
      float2 xv=*(const float2*)(X+(size_t)(b*NN+i)*HH+2*tid);
      *(uint32_t*)(sm+OFF_HIS+tid*4)=f2bf(xv.x,xv.y);
    } else if(tid>=64&&tid<96){
      ((float4*)(sm+OFF_AI))[tid-64]=((const float4*)(g_A+(size_t)(b*NN+i)*HH))[tid-64];
    }
    __syncthreads();

    {
      int j=tid&127, sec=tid>>7;
      for(int c8=0;c8<16;c8++){
        uint32_t v[4];
#pragma unroll
        for(int q=0;q<4;q++){
          int kp=c8*4+q;
          __nv_bfloat162 h2=*(__nv_bfloat162*)(sm+OFF_HIS+kp*4);
          __nv_bfloat162 x2=*(__nv_bfloat162*)(sm+OFF_XJ+(kp*129+j)*4);
          __nv_bfloat162 r=sec?__hmul2(h2,x2):__habs2(__hsub2(h2,x2));
          v[q]=*(uint32_t*)&r;
        }
        *(float4*)(sm+OFF_F+foff((uint32_t)j,(uint32_t)(sec*128+c8*8)))=*(float4*)v;
      }
      if(tid<128){
        float bv=fminf(fmaxf(base[((size_t)(b*NN)+i)*NN+j0+j],-20.f),20.f);
        float cv=fminf(fmaxf(comp[((size_t)(b*NN)+i)*NN+j0+j],-20.f),20.f);
        float sb=1.f/(1.f+__expf(-bv)), sc=1.f/(1.f+__expf(-cv));
        uint32_t v[4]={f2bf(bv,sb),f2bf(cv,sc),0u,0u};
        *(float4*)(sm+OFF_F+foff((uint32_t)j,256))=*(float4*)v;
      }
    }
    __syncthreads();

    float c[2][8][4];
#pragma unroll
    for(int mt=0;mt<2;mt++)
#pragma unroll
      for(int nt=0;nt<8;nt++)
#pragma unroll
        for(int e=0;e<4;e++) c[mt][nt][e]=0.f;

    for(int ks=0;ks<17;ks++){
      uint32_t k2=(uint32_t)ks*32u;
      uint32_t a[2][4], bf[8][2];
      LDSM4(a[0][0],a[0][1],a[0][2],a[0][3], smb+((offA+k2)^xr));
      LDSM4(a[1][0],a[1][1],a[1][2],a[1][3], smb+((offA+16*576u+k2)^xr));
#pragma unroll
      for(int q=0;q<4;q++){
        LDSM4(bf[2*q][0],bf[2*q][1],bf[2*q+1][0],bf[2*q+1][1], smb+((offB[q]+k2)^xr));
      }
#pragma unroll
      for(int mt=0;mt<2;mt++)
#pragma unroll
        for(int nt=0;nt<8;nt++)
          MMA16816(c[mt][nt],a[mt],bf[nt]);
    }

    {
      int ch=hw>>6;
      float p[4];
#pragma unroll
      for(int r=0;r<4;r++) p[r]=0.f;
#pragma unroll
      for(int mt=0;mt<2;mt++){
#pragma unroll
        for(int rh=0;rh<2;rh++){
          int j=jw+mt*16+rh*8+(lane>>2);
#pragma unroll
          for(int nt=0;nt<8;nt++){
            int hb=hw+nt*8+2*(lane&3);
            float2 ai=*(float2*)(sm+OFF_AI+hb*4);
            float2 w2=*(float2*)(sm+OFF_W2+hb*4);
            float2 bj=__bfloat1622float2(*(__nv_bfloat162*)(sm+OFF_BJ+(j*66+(hb>>1))*4));
            p[mt*2+rh]+=fmaxf(c[mt][nt][rh*2]  +ai.x+bj.x,0.f)*w2.x
                       +fmaxf(c[mt][nt][rh*2+1]+ai.y+bj.y,0.f)*w2.y;
          }
        }
      }
#pragma unroll
      for(int r=0;r<4;r++){
        p[r]+=__shfl_xor_sync(0xffffffffu,p[r],1);
        p[r]+=__shfl_xor_sync(0xffffffffu,p[r],2);
      }
      if((lane&3)==0){
#pragma unroll
        for(int r=0;r<4;r++){
          int j=jw+(r>>1)*16+(r&1)*8+(lane>>2);
          *(float*)(sm+OFF_RED+(j*2+ch)*4)=p[r];
        }
      }
    }
    __syncthreads();
    if(tid<128){
      float v=*(float*)(sm+OFF_RED+tid*8)+*(float*)(sm+OFF_RED+tid*8+4)+b2v;
      out[((size_t)(b*NN)+i)*NN+j0+tid]=v;
    }
    __syncthreads();
  }
}

// ---- Kernel 3: symmetrize + diagonal ----
__global__ void symmetrize(float* __restrict__ out){
  int idx=blockIdx.x*256+threadIdx.x;
  int b=idx>>16, r=idx&65535, i=r>>8, j=r&255;
  float* ob=out+(size_t)b*NN*NN;
  if(j>i){
    float v=0.5f*(ob[i*NN+j]+ob[j*NN+i]);
    ob[i*NN+j]=v; ob[j*NN+i]=v;
  } else if(j==i) ob[i*NN+i]=-1e9f;
}

extern "C" void kernel_launch(void* const* d_in, const int* in_sizes, int n_in,
                              void* d_out, int out_size){
  const float* X   =(const float*)d_in[0];
  const float* base=(const float*)d_in[1];
  const float* comp=(const float*)d_in[2];
  const float* W1  =(const float*)d_in[3];
  const float* b1  =(const float*)d_in[4];
  const float* W2  =(const float*)d_in[5];
  const float* b2  =(const float*)d_in[6];
  float* out=(float*)d_out;

  precompute_ab<<<NB*NN/4,256>>>(X,W1,b1);
  cudaFuncSetAttribute(pair_gemm,cudaFuncAttributeMaxDynamicSharedMemorySize,SMEM_TOT);
  dim3 g(2,16,NB);
  pair_gemm<<<g,256,SMEM_TOT>>>(X,base,comp,W1,W2,b2,out);
  symmetrize<<<NB*NN*NN/256,256>>>(out);
}

// round 9
// speedup vs baseline: 2.3214x; 1.0247x over previous
#include <cuda_runtime.h>
#include <cuda_bf16.h>
#include <cstdint>

#define NB 4
#define NN 256
#define HH 128
typedef unsigned long long ull;

__device__ float g_A[NB*NN*HH];
__device__ float g_Bv[NB*NN*HH];

// smem byte offsets (dynamic, pair_gemm)
#define OFF_F    0          // F image  [128][288] bf16 (swizzled)
#define OFF_W    73728      // Wt image [128][288] bf16 (swizzled)
#define OFF_XJ   147456     // Xj pairs u32 [64][129]
#define OFF_BJ   180480     // Bj pairs u32 [128][66]
#define OFF_HIS  214272     // hi pairs u32 [64]
#define OFF_AI   214528     // f32[128]
#define OFF_W2   215040     // f32[128]
#define OFF_RED  215552     // f32[128][2]
#define SMEM_TOT 216576

__device__ __forceinline__ uint32_t s32(const void* p){
  uint32_t a; asm("{ .reg .u64 t; cvta.to.shared.u64 t, %1; cvt.u32.u64 %0, t; }":"=r"(a):"l"(p)); return a;
}
__device__ __forceinline__ uint32_t foff(uint32_t r, uint32_t k){
  return ((r*576u + k*2u) ^ ((r&7u)<<4));
}
__device__ __forceinline__ uint32_t f2bf(float a,float b){
  __nv_bfloat162 t=__floats2bfloat162_rn(a,b); return *(uint32_t*)&t;
}
__device__ __forceinline__ void cpa16(void* dst,const void* src){
  unsigned d=(unsigned)__cvta_generic_to_shared(dst);
  asm volatile("cp.async.cg.shared.global [%0],[%1],16;\n"::"r"(d),"l"(src));
}
__device__ __forceinline__ void cpcommit(){ asm volatile("cp.async.commit_group;\n"); }
__device__ __forceinline__ void cpwait0(){ asm volatile("cp.async.wait_group 0;\n"); }

#define LDSM4(r0,r1,r2,r3,a) asm volatile( \
  "ldmatrix.sync.aligned.m8n8.x4.shared.b16 {%0,%1,%2,%3},[%4];" \
  :"=r"(r0),"=r"(r1),"=r"(r2),"=r"(r3):"r"(a))
#define MMA16816(c,a,b) asm volatile( \
  "mma.sync.aligned.m16n8k16.row.col.f32.bf16.bf16.f32 " \
  "{%0,%1,%2,%3},{%4,%5,%6,%7},{%8,%9},{%0,%1,%2,%3};" \
  :"+f"((c)[0]),"+f"((c)[1]),"+f"((c)[2]),"+f"((c)[3]) \
  :"r"((a)[0]),"r"((a)[1]),"r"((a)[2]),"r"((a)[3]),"r"((b)[0]),"r"((b)[1]))

// ---- Kernel 1: per-node halves, smem-staged W1 (LDS-fed FMA) ----
__global__ void __launch_bounds__(256)
precompute_ab(const float* __restrict__ X,
              const float* __restrict__ W1,
              const float* __restrict__ b1){
  __shared__ __align__(16) float Xs[8*HH];        // 4KB
  __shared__ __align__(16) float Ws[2][32*HH];    // 32KB
  int r0=blockIdx.x*8;
  int tid=threadIdx.x;
  int h=tid&127, s=tid>>7;     // s=0 -> A half (W1 rows 0..127), s=1 -> B half (128..255)

  for(int e=tid;e<8*HH/4;e+=256)
    ((float4*)Xs)[e]=((const float4*)(X+(size_t)r0*HH))[e];

  float acc[8]={0.f,0.f,0.f,0.f,0.f,0.f,0.f,0.f};

  for(int c=0;c<4;c++){
    // stage W1 chunk: rows [c*32, c*32+32) of each half -> Ws[s][kk][h]
    for(int e=tid;e<2*32*HH/4;e+=256){
      int sh=e>=(32*HH/4);
      int le=e-sh*(32*HH/4);
      cpa16((float4*)Ws[sh]+le,
            (const float4*)(W1+((size_t)(sh*HH+c*32))*HH)+le);
    }
    cpcommit(); cpwait0();
    __syncthreads();
    const float* wp=Ws[s];
#pragma unroll 8
    for(int kk=0;kk<32;kk++){
      float wv=wp[kk*HH+h];
      int k=c*32+kk;
#pragma unroll
      for(int r=0;r<8;r++) acc[r]+=Xs[r*HH+k]*wv;
    }
    __syncthreads();
  }

  if(s==0){
    float bb=b1[h];
#pragma unroll
    for(int r=0;r<8;r++) g_A[(size_t)(r0+r)*HH+h]=acc[r]+bb;
  } else {
#pragma unroll
    for(int r=0;r<8;r++) g_Bv[(size_t)(r0+r)*HH+h]=acc[r];
  }
}

// ---- Kernel 2: HMMA pairwise GEMM + fused epilogue (unchanged, validated) ----
extern __shared__ __align__(1024) char dynsm[];

__global__ void __launch_bounds__(256,1)
pair_gemm(const float* __restrict__ X,const float* __restrict__ base,
          const float* __restrict__ comp,const float* __restrict__ W1,
          const float* __restrict__ W2,const float* __restrict__ b2,
          float* __restrict__ out){
  char* sm=dynsm;
  uint32_t smb=s32(sm);
  int tid=threadIdx.x, w=tid>>5, lane=tid&31;
  int jt=blockIdx.x, ig=blockIdx.y, b=blockIdx.z;
  int j0=jt*128;
  int jw=(w&3)*32, hw=(w>>2)*64;
  float b2v=b2[0];

  {
    int h=tid&127, halfk=tid>>7;
    for(int c8=0;c8<16;c8++){
      int k0=halfk*128+c8*8;
      uint32_t v[4];
#pragma unroll
      for(int q=0;q<4;q++)
        v[q]=f2bf(W1[(256+k0+2*q)*HH+h], W1[(256+k0+2*q+1)*HH+h]);
      *(float4*)(sm+OFF_W+foff(h,k0))=*(float4*)v;
    }
    if(tid<128){
      uint32_t v[4]={f2bf(W1[512*HH+h],W1[513*HH+h]),
                     f2bf(W1[514*HH+h],W1[515*HH+h]),0u,0u};
      *(float4*)(sm+OFF_W+foff(h,256))=*(float4*)v;
      uint32_t z[4]={0u,0u,0u,0u};
      *(float4*)(sm+OFF_W+foff(h,264))=*(float4*)z;
      *(float4*)(sm+OFF_F+foff(h,264))=*(float4*)z;
    }
  }
  for(int idx=tid;idx<64*128;idx+=256){
    int kp=idx&63, j=idx>>6;
    float2 xv=*(const float2*)(X+(size_t)(b*NN+j0+j)*HH+2*kp);
    *(uint32_t*)(sm+OFF_XJ+(kp*129+j)*4)=f2bf(xv.x,xv.y);
  }
  for(int idx=tid;idx<64*128;idx+=256){
    int hp=idx&63, j=idx>>6;
    float2 bv=*(const float2*)(g_Bv+(size_t)(b*NN+j0+j)*HH+2*hp);
    *(uint32_t*)(sm+OFF_BJ+(j*66+hp)*4)=f2bf(bv.x,bv.y);
  }
  if(tid<32) ((float4*)(sm+OFF_W2))[tid]=((const float4*)W2)[tid];
  __syncthreads();

  uint32_t xr=(uint32_t)((lane&7)<<4);
  uint32_t offA = OFF_F + (uint32_t)(jw+(lane&15))*576u + (uint32_t)((lane>>4)*8)*2u;
  uint32_t offB[4];
#pragma unroll
  for(int q=0;q<4;q++){
    uint32_t rB=(uint32_t)(hw + q*16 + (lane&7) + ((lane>>4)<<3));
    offB[q]= OFF_W + rB*576u + (uint32_t)(((lane>>3)&1)*8)*2u;
  }

  for(int itn=0;itn<16;itn++){
    int i=ig*16+itn;
    if(tid<64){
      float2 xv=*(const float2*)(X+(size_t)(b*NN+i)*HH+2*tid);
      *(uint32_t*)(sm+OFF_HIS+tid*4)=f2bf(xv.x,xv.y);
    } else if(tid>=64&&tid<96){
      ((float4*)(sm+OFF_AI))[tid-64]=((const float4*)(g_A+(size_t)(b*NN+i)*HH))[tid-64];
    }
    __syncthreads();

    {
      int j=tid&127, sec=tid>>7;
      for(int c8=0;c8<16;c8++){
        uint32_t v[4];
#pragma unroll
        for(int q=0;q<4;q++){
          int kp=c8*4+q;
          __nv_bfloat162 h2=*(__nv_bfloat162*)(sm+OFF_HIS+kp*4);
          __nv_bfloat162 x2=*(__nv_bfloat162*)(sm+OFF_XJ+(kp*129+j)*4);
          __nv_bfloat162 r=sec?__hmul2(h2,x2):__habs2(__hsub2(h2,x2));
          v[q]=*(uint32_t*)&r;
        }
        *(float4*)(sm+OFF_F+foff((uint32_t)j,(uint32_t)(sec*128+c8*8)))=*(float4*)v;
      }
      if(tid<128){
        float bv=fminf(fmaxf(base[((size_t)(b*NN)+i)*NN+j0+j],-20.f),20.f);
        float cv=fminf(fmaxf(comp[((size_t)(b*NN)+i)*NN+j0+j],-20.f),20.f);
        float sb=1.f/(1.f+__expf(-bv)), sc=1.f/(1.f+__expf(-cv));
        uint32_t v[4]={f2bf(bv,sb),f2bf(cv,sc),0u,0u};
        *(float4*)(sm+OFF_F+foff((uint32_t)j,256))=*(float4*)v;
      }
    }
    __syncthreads();

    float c[2][8][4];
#pragma unroll
    for(int mt=0;mt<2;mt++)
#pragma unroll
      for(int nt=0;nt<8;nt++)
#pragma unroll
        for(int e=0;e<4;e++) c[mt][nt][e]=0.f;

    for(int ks=0;ks<17;ks++){
      uint32_t k2=(uint32_t)ks*32u;
      uint32_t a[2][4], bf[8][2];
      LDSM4(a[0][0],a[0][1],a[0][2],a[0][3], smb+((offA+k2)^xr));
      LDSM4(a[1][0],a[1][1],a[1][2],a[1][3], smb+((offA+16*576u+k2)^xr));
#pragma unroll
      for(int q=0;q<4;q++){
        LDSM4(bf[2*q][0],bf[2*q][1],bf[2*q+1][0],bf[2*q+1][1], smb+((offB[q]+k2)^xr));
      }
#pragma unroll
      for(int mt=0;mt<2;mt++)
#pragma unroll
        for(int nt=0;nt<8;nt++)
          MMA16816(c[mt][nt],a[mt],bf[nt]);
    }

    {
      int ch=hw>>6;
      float p[4];
#pragma unroll
      for(int r=0;r<4;r++) p[r]=0.f;
#pragma unroll
      for(int mt=0;mt<2;mt++){
#pragma unroll
        for(int rh=0;rh<2;rh++){
          int j=jw+mt*16+rh*8+(lane>>2);
#pragma unroll
          for(int nt=0;nt<8;nt++){
            int hb=hw+nt*8+2*(lane&3);
            float2 ai=*(float2*)(sm+OFF_AI+hb*4);
            float2 w2=*(float2*)(sm+OFF_W2+hb*4);
            float2 bj=__bfloat1622float2(*(__nv_bfloat162*)(sm+OFF_BJ+(j*66+(hb>>1))*4));
            p[mt*2+rh]+=fmaxf(c[mt][nt][rh*2]  +ai.x+bj.x,0.f)*w2.x
                       +fmaxf(c[mt][nt][rh*2+1]+ai.y+bj.y,0.f)*w2.y;
          }
        }
      }
#pragma unroll
      for(int r=0;r<4;r++){
        p[r]+=__shfl_xor_sync(0xffffffffu,p[r],1);
        p[r]+=__shfl_xor_sync(0xffffffffu,p[r],2);
      }
      if((lane&3)==0){
#pragma unroll
        for(int r=0;r<4;r++){
          int j=jw+(r>>1)*16+(r&1)*8+(lane>>2);
          *(float*)(sm+OFF_RED+(j*2+ch)*4)=p[r];
        }
      }
    }
    __syncthreads();
    if(tid<128){
      float v=*(float*)(sm+OFF_RED+tid*8)+*(float*)(sm+OFF_RED+tid*8+4)+b2v;
      out[((size_t)(b*NN)+i)*NN+j0+tid]=v;
    }
    __syncthreads();
  }
}

// ---- Kernel 3: symmetrize + diagonal ----
__global__ void symmetrize(float* __restrict__ out){
  int idx=blockIdx.x*256+threadIdx.x;
  int b=idx>>16, r=idx&65535, i=r>>8, j=r&255;
  float* ob=out+(size_t)b*NN*NN;
  if(j>i){
    float v=0.5f*(ob[i*NN+j]+ob[j*NN+i]);
    ob[i*NN+j]=v; ob[j*NN+i]=v;
  } else if(j==i) ob[i*NN+i]=-1e9f;
}

extern "C" void kernel_launch(void* const* d_in, const int* in_sizes, int n_in,
                              void* d_out, int out_size){
  const float* X   =(const float*)d_in[0];
  const float* base=(const float*)d_in[1];
  const float* comp=(const float*)d_in[2];
  const float* W1  =(const float*)d_in[3];
  const float* b1  =(const float*)d_in[4];
  const float* W2  =(const float*)d_in[5];
  const float* b2  =(const float*)d_in[6];
  float* out=(float*)d_out;

  precompute_ab<<<NB*NN/8,256>>>(X,W1,b1);
  cudaFuncSetAttribute(pair_gemm,cudaFuncAttributeMaxDynamicSharedMemorySize,SMEM_TOT);
  dim3 g(2,16,NB);
  pair_gemm<<<g,256,SMEM_TOT>>>(X,base,comp,W1,W2,b2,out);
  symmetrize<<<NB*NN*NN/256,256>>>(out);
}